// round 16
// baseline (speedup 1.0000x reference)
#include <cuda_runtime.h>
#include <cuda_fp16.h>
#include <cstdint>

#define N_NODES 100000
#define N_EDGES 1600000
#define N_GRAPH 100
#define IN_DIM 64
#define LATENT 128
#define LN_EPS 1e-5f

#define PDL_TRIGGER() asm volatile("griddepcontrol.launch_dependents;" ::: "memory")
#define PDL_WAIT()    asm volatile("griddepcontrol.wait;" ::: "memory")

// ---------------- scratch (device globals; no allocation allowed) ----------------
__device__ uint32_t g_h16[(size_t)N_NODES * 64];     // node state, packed half2
__device__ uint32_t g_x16[(size_t)N_NODES * 64];     // xs, packed half2
__device__ int   g_cs[N_NODES];
__device__ int   g_cr[N_NODES];
__device__ float g_invs[N_NODES];
__device__ float g_invr[N_NODES];
__device__ int   g_start[N_NODES];
__device__ int   g_fill[N_NODES];
__device__ int   g_csr[N_EDGES];
__device__ int   g_cursor;
#define WCONV_WORDS (4096 + 4 * 8192)
__device__ uint32_t g_whi[WCONV_WORDS];
__device__ uint32_t g_wlo[WCONV_WORDS];

// ---------------- degree / CSR kernels (int4-vectorized) ----------------
__global__ void k_zero_deg() {
    int i = blockIdx.x * blockDim.x + threadIdx.x;
    if (i < N_NODES) { g_cs[i] = 0; g_cr[i] = 0; }
    if (i == 0) g_cursor = 0;
}
__global__ void k_count(const int* __restrict__ senders, const int* __restrict__ receivers) {
    int t = blockIdx.x * blockDim.x + threadIdx.x;
    if (t < N_EDGES / 4) {
        int4 s = ((const int4*)senders)[t];
        int4 r = ((const int4*)receivers)[t];
        atomicAdd(&g_cs[s.x], 1); atomicAdd(&g_cs[s.y], 1);
        atomicAdd(&g_cs[s.z], 1); atomicAdd(&g_cs[s.w], 1);
        atomicAdd(&g_cr[r.x], 1); atomicAdd(&g_cr[r.y], 1);
        atomicAdd(&g_cr[r.z], 1); atomicAdd(&g_cr[r.w], 1);
    }
}
__global__ void k_inv() {
    int i = blockIdx.x * blockDim.x + threadIdx.x;
    if (i < N_NODES) {
        g_invs[i] = rsqrtf((float)(g_cs[i] + 1));
        g_invr[i] = rsqrtf((float)(g_cr[i] + 1));
        int st = atomicAdd(&g_cursor, g_cr[i]);
        g_start[i] = st;
        g_fill[i] = st;
    }
}
__global__ void k_fill(const int* __restrict__ senders, const int* __restrict__ receivers) {
    int t = blockIdx.x * blockDim.x + threadIdx.x;
    if (t < N_EDGES / 4) {
        int4 s = ((const int4*)senders)[t];
        int4 r = ((const int4*)receivers)[t];
        g_csr[atomicAdd(&g_fill[r.x], 1)] = s.x;
        g_csr[atomicAdd(&g_fill[r.y], 1)] = s.y;
        g_csr[atomicAdd(&g_fill[r.z], 1)] = s.z;
        g_csr[atomicAdd(&g_fill[r.w], 1)] = s.w;
    }
}

// ---------------- fp16 helpers ----------------
__device__ __forceinline__ void hilo(float x, __half& h, float& res) {
    h = __float2half_rn(x);
    res = x - __half2float(h);
}
__device__ __forceinline__ uint32_t pack2(__half a, __half b) {
    __half2 h = __halves2half2(a, b);
    return *(uint32_t*)&h;
}
__device__ __forceinline__ void mma_f16(float c[4], const uint32_t a[4],
                                        uint32_t b0, uint32_t b1) {
    asm volatile(
        "mma.sync.aligned.m16n8k16.row.col.f32.f16.f16.f32 "
        "{%0,%1,%2,%3}, {%4,%5,%6,%7}, {%8,%9}, {%0,%1,%2,%3};"
        : "+f"(c[0]), "+f"(c[1]), "+f"(c[2]), "+f"(c[3])
        : "r"(a[0]), "r"(a[1]), "r"(a[2]), "r"(a[3]),
          "r"(b0), "r"(b1));
}
__device__ __forceinline__ void acc8(float* a, uint4 v) {
    float2 e;
    e = __half22float2(*(__half2*)&v.x); a[0] += e.x; a[1] += e.y;
    e = __half22float2(*(__half2*)&v.y); a[2] += e.x; a[3] += e.y;
    e = __half22float2(*(__half2*)&v.z); a[4] += e.x; a[5] += e.y;
    e = __half22float2(*(__half2*)&v.w); a[6] += e.x; a[7] += e.y;
}

// ---------------- weight pre-conversion ----------------
__global__ void k_wconv(const float* __restrict__ embed_w, const float* __restrict__ mlp_w) {
    int i = blockIdx.x * blockDim.x + threadIdx.x;
    if (i >= WCONV_WORDS) return;
    float v0, v1;
    if (i < 4096) {
        int n = i >> 5, kp = i & 31;
        v0 = embed_w[(size_t)(2 * kp) * 128 + n];
        v1 = embed_w[(size_t)(2 * kp + 1) * 128 + n];
    } else {
        int j = i - 4096;
        int g = j >> 13;
        int r = j & 8191;
        int n = r >> 6, kp = r & 63;
        const float* W = mlp_w + (size_t)g * 128 * 128;
        v0 = W[(size_t)(2 * kp) * 128 + n];
        v1 = W[(size_t)(2 * kp + 1) * 128 + n];
    }
    __half h0, h1; float r0, r1;
    hilo(v0, h0, r0); hilo(v1, h1, r1);
    g_whi[i] = pack2(h0, h1);
    g_wlo[i] = pack2(__float2half_rn(r0), __float2half_rn(r1));
}

#define S2  36
#define S2F 68
#define TILEW (128 * S2)

// ---------------- embed GEMM: fp32 A, hi/lo split (3 passes), K=64 ----------------
__global__ __launch_bounds__(512, 2)
void k_embed(const float* __restrict__ A,
             const uint32_t* __restrict__ Whi, const uint32_t* __restrict__ Wlo,
             const float* __restrict__ bias, uint32_t* __restrict__ C16, int M) {
    extern __shared__ uint32_t sm[];
    uint32_t* sAhi = sm;
    uint32_t* sBhi = sm + TILEW;
    uint32_t* sBlo = sm + 2 * TILEW;
    uint32_t* sAlo = sm + 3 * TILEW;
    float*    sBias = (float*)(sm + 4 * TILEW);

    PDL_TRIGGER();

    const int tid  = threadIdx.x;
    const int lane = tid & 31;
    const int wid  = tid >> 5;
    const int grp  = lane >> 2;
    const int tig  = lane & 3;
    const int wm   = wid & 3;
    const int wn   = wid >> 2;
    const int row0 = blockIdx.x * 128;

    if (tid < 128) sBias[tid] = bias[tid];

    float acc[2][4][4];
#pragma unroll
    for (int i = 0; i < 2; i++)
#pragma unroll
        for (int j = 0; j < 4; j++)
#pragma unroll
            for (int q = 0; q < 4; q++) acc[i][j][q] = 0.f;

#pragma unroll
    for (int it = 0; it < 4; it++) {
        int i  = tid + it * 512;
        int r  = i >> 4;
        int c4 = (i & 15) * 4;
        float4 v = make_float4(0.f, 0.f, 0.f, 0.f);
        if (row0 + r < M)
            v = *(const float4*)&A[(size_t)(row0 + r) * 64 + c4];
        __half h0, h1, h2, h3; float r0, r1, r2, r3;
        hilo(v.x, h0, r0); hilo(v.y, h1, r1);
        hilo(v.z, h2, r2); hilo(v.w, h3, r3);
        int w = r * S2 + (c4 >> 1);
        *(uint2*)&sAhi[w] = make_uint2(pack2(h0, h1), pack2(h2, h3));
        *(uint2*)&sAlo[w] = make_uint2(
            pack2(__float2half_rn(r0), __float2half_rn(r1)),
            pack2(__float2half_rn(r2), __float2half_rn(r3)));
    }
#pragma unroll
    for (int it = 0; it < 2; it++) {
        int i = tid + it * 512;
        int n = i >> 3;
        int q = (i & 7) * 4;
        if (q < 32) {
            *(uint4*)&sBhi[n * S2 + q] = *(const uint4*)&Whi[n * 32 + q];
            *(uint4*)&sBlo[n * S2 + q] = *(const uint4*)&Wlo[n * 32 + q];
        }
    }
    __syncthreads();

#pragma unroll
    for (int ks = 0; ks < 4; ks++) {
        const int kb = ks * 8;
        uint32_t aH[2][4], aL[2][4];
#pragma unroll
        for (int mt = 0; mt < 2; mt++) {
            int base = (wm * 32 + mt * 16 + grp) * S2 + kb + tig;
            aH[mt][0] = sAhi[base];
            aH[mt][1] = sAhi[base + 8 * S2];
            aH[mt][2] = sAhi[base + 4];
            aH[mt][3] = sAhi[base + 8 * S2 + 4];
            aL[mt][0] = sAlo[base];
            aL[mt][1] = sAlo[base + 8 * S2];
            aL[mt][2] = sAlo[base + 4];
            aL[mt][3] = sAlo[base + 8 * S2 + 4];
        }
#pragma unroll
        for (int nt = 0; nt < 4; nt++) {
            int bb = (wn * 32 + nt * 8 + grp) * S2 + kb + tig;
            uint32_t bh0 = sBhi[bb], bh1 = sBhi[bb + 4];
            uint32_t bl0 = sBlo[bb], bl1 = sBlo[bb + 4];
#pragma unroll
            for (int mt = 0; mt < 2; mt++) {
                mma_f16(acc[mt][nt], aH[mt], bh0, bh1);
                mma_f16(acc[mt][nt], aH[mt], bl0, bl1);
                mma_f16(acc[mt][nt], aL[mt], bh0, bh1);
            }
        }
    }

#pragma unroll
    for (int mt = 0; mt < 2; mt++) {
        int ra = row0 + wm * 32 + mt * 16 + grp;
        int rb = ra + 8;
#pragma unroll
        for (int nt = 0; nt < 4; nt++) {
            int col = wn * 32 + nt * 8 + 2 * tig;
            float b0 = sBias[col], b1 = sBias[col + 1];
            __half2 pa2 = __floats2half2_rn(acc[mt][nt][0] + b0, acc[mt][nt][1] + b1);
            __half2 pb2 = __floats2half2_rn(acc[mt][nt][2] + b0, acc[mt][nt][3] + b1);
            if (ra < M) C16[(size_t)ra * 64 + (col >> 1)] = *(uint32_t*)&pa2;
            if (rb < M) C16[(size_t)rb * 64 + (col >> 1)] = *(uint32_t*)&pb2;
        }
    }
}
#define SM_EMBED (4 * TILEW * 4 + 128 * 4)

// ---------------- fused 2-layer MLP ----------------
__global__ __launch_bounds__(512, 2)
void k_mlp(const uint32_t* __restrict__ A16,
           const uint32_t* __restrict__ W1hi, const uint32_t* __restrict__ W1lo,
           const uint32_t* __restrict__ W2hi, const uint32_t* __restrict__ W2lo,
           const float* __restrict__ b1, const float* __restrict__ b2,
           uint32_t* __restrict__ C16, int M) {
    extern __shared__ uint32_t sm[];
    uint32_t* sA   = sm;
    uint32_t* sBhi = sm + 128 * S2F;
    uint32_t* sBlo = sBhi + TILEW;
    float*    sB1  = (float*)(sBlo + TILEW);
    float*    sB2  = sB1 + 128;

    PDL_TRIGGER();

    const int tid  = threadIdx.x;
    const int lane = tid & 31;
    const int wid  = tid >> 5;
    const int grp  = lane >> 2;
    const int tig  = lane & 3;
    const int wm   = wid & 3;
    const int wn   = wid >> 2;
    const int row0 = blockIdx.x * 128;

    if (tid < 128) { sB1[tid] = b1[tid]; sB2[tid] = b2[tid]; }

#pragma unroll
    for (int it = 0; it < 2; it++) {
        int i = tid + it * 512;
        int n = i >> 3;
        int q = (i & 7) * 4;
        int gw = n * 64 + q;
        *(uint4*)&sBhi[n * S2 + q] = *(const uint4*)&W1hi[gw];
        *(uint4*)&sBlo[n * S2 + q] = *(const uint4*)&W1lo[gw];
    }

    PDL_WAIT();

#pragma unroll
    for (int it = 0; it < 4; it++) {
        int i = tid + it * 512;
        int r = i >> 4;
        int q = (i & 15) * 4;
        uint4 v = make_uint4(0, 0, 0, 0);
        if (row0 + r < M)
            v = *(const uint4*)&A16[(size_t)(row0 + r) * 64 + q];
        *(uint4*)&sA[r * S2F + q] = v;
    }

    float acc[2][4][4];
#pragma unroll
    for (int i = 0; i < 2; i++)
#pragma unroll
        for (int j = 0; j < 4; j++)
#pragma unroll
            for (int q = 0; q < 4; q++) acc[i][j][q] = 0.f;

    // ================= GEMM 1 =================
    for (int ch = 0; ch < 2; ch++) {
        if (ch) {
            __syncthreads();
#pragma unroll
            for (int it = 0; it < 2; it++) {
                int i = tid + it * 512;
                int n = i >> 3;
                int q = (i & 7) * 4;
                int gw = n * 64 + 32 + q;
                *(uint4*)&sBhi[n * S2 + q] = *(const uint4*)&W1hi[gw];
                *(uint4*)&sBlo[n * S2 + q] = *(const uint4*)&W1lo[gw];
            }
        }
        __syncthreads();
#pragma unroll
        for (int ks = 0; ks < 4; ks++) {
            const int kb = ks * 8;
            uint32_t aH[2][4];
#pragma unroll
            for (int mt = 0; mt < 2; mt++) {
                int base = (wm * 32 + mt * 16 + grp) * S2F + ch * 32 + kb + tig;
                aH[mt][0] = sA[base];
                aH[mt][1] = sA[base + 8 * S2F];
                aH[mt][2] = sA[base + 4];
                aH[mt][3] = sA[base + 8 * S2F + 4];
            }
#pragma unroll
            for (int nt = 0; nt < 4; nt++) {
                int bb = (wn * 32 + nt * 8 + grp) * S2 + kb + tig;
                uint32_t bh0 = sBhi[bb], bh1 = sBhi[bb + 4];
                uint32_t bl0 = sBlo[bb], bl1 = sBlo[bb + 4];
#pragma unroll
                for (int mt = 0; mt < 2; mt++) {
                    mma_f16(acc[mt][nt], aH[mt], bh0, bh1);
                    mma_f16(acc[mt][nt], aH[mt], bl0, bl1);
                }
            }
        }
    }
    __syncthreads();

#pragma unroll
    for (int mt = 0; mt < 2; mt++) {
        int lr = wm * 32 + mt * 16 + grp;
#pragma unroll
        for (int nt = 0; nt < 4; nt++) {
            int col = wn * 32 + nt * 8 + 2 * tig;
            float b0 = sB1[col], bq = sB1[col + 1];
            float v0 = fmaxf(acc[mt][nt][0] + b0, 0.f);
            float v1 = fmaxf(acc[mt][nt][1] + bq, 0.f);
            float v2 = fmaxf(acc[mt][nt][2] + b0, 0.f);
            float v3 = fmaxf(acc[mt][nt][3] + bq, 0.f);
            sA[lr * S2F + (col >> 1)]       = pack2(__float2half_rn(v0), __float2half_rn(v1));
            sA[(lr + 8) * S2F + (col >> 1)] = pack2(__float2half_rn(v2), __float2half_rn(v3));
            acc[mt][nt][0] = 0.f; acc[mt][nt][1] = 0.f;
            acc[mt][nt][2] = 0.f; acc[mt][nt][3] = 0.f;
        }
    }

    // ================= GEMM 2 =================
    for (int ch = 0; ch < 2; ch++) {
        if (ch) __syncthreads();
#pragma unroll
        for (int it = 0; it < 2; it++) {
            int i = tid + it * 512;
            int n = i >> 3;
            int q = (i & 7) * 4;
            int gw = n * 64 + ch * 32 + q;
            *(uint4*)&sBhi[n * S2 + q] = *(const uint4*)&W2hi[gw];
            *(uint4*)&sBlo[n * S2 + q] = *(const uint4*)&W2lo[gw];
        }
        __syncthreads();
#pragma unroll
        for (int ks = 0; ks < 4; ks++) {
            const int kb = ks * 8;
            uint32_t aH[2][4];
#pragma unroll
            for (int mt = 0; mt < 2; mt++) {
                int base = (wm * 32 + mt * 16 + grp) * S2F + ch * 32 + kb + tig;
                aH[mt][0] = sA[base];
                aH[mt][1] = sA[base + 8 * S2F];
                aH[mt][2] = sA[base + 4];
                aH[mt][3] = sA[base + 8 * S2F + 4];
            }
#pragma unroll
            for (int nt = 0; nt < 4; nt++) {
                int bb = (wn * 32 + nt * 8 + grp) * S2 + kb + tig;
                uint32_t bh0 = sBhi[bb], bh1 = sBhi[bb + 4];
                uint32_t bl0 = sBlo[bb], bl1 = sBlo[bb + 4];
#pragma unroll
                for (int mt = 0; mt < 2; mt++) {
                    mma_f16(acc[mt][nt], aH[mt], bh0, bh1);
                    mma_f16(acc[mt][nt], aH[mt], bl0, bl1);
                }
            }
        }
    }

#pragma unroll
    for (int mt = 0; mt < 2; mt++) {
        int ra = row0 + wm * 32 + mt * 16 + grp;
        int rb = ra + 8;
        float sa = (ra < M) ? g_invs[ra] : 0.f;
        float sb = (rb < M) ? g_invs[rb] : 0.f;
#pragma unroll
        for (int nt = 0; nt < 4; nt++) {
            int col = wn * 32 + nt * 8 + 2 * tig;
            float b0 = sB2[col], bq = sB2[col + 1];
            float v0 = fmaxf(acc[mt][nt][0] + b0, 0.f) * sa;
            float v1 = fmaxf(acc[mt][nt][1] + bq, 0.f) * sa;
            float v2 = fmaxf(acc[mt][nt][2] + b0, 0.f) * sb;
            float v3 = fmaxf(acc[mt][nt][3] + bq, 0.f) * sb;
            __half2 pa2 = __floats2half2_rn(v0, v1);
            __half2 pb2 = __floats2half2_rn(v2, v3);
            if (ra < M) C16[(size_t)ra * 64 + (col >> 1)] = *(uint32_t*)&pa2;
            if (rb < M) C16[(size_t)rb * 64 + (col >> 1)] = *(uint32_t*)&pb2;
        }
    }
}
#define SM_MLP ((128 * S2F + 2 * TILEW) * 4 + 256 * 4)

// ---------------- fused CSR gather + skip + LayerNorm: HALF-WARP per node ----------------
// 16 threads/node, each owns 4 words (8 halves) -> neighbor row = 16 x LDG.128.
__global__ __launch_bounds__(256)
void k_gln(const uint32_t* __restrict__ xs16, uint32_t* __restrict__ h16,
           const float* __restrict__ scale, const float* __restrict__ offset) {
    PDL_TRIGGER();
    int node = (blockIdx.x * blockDim.x + threadIdx.x) >> 4;
    int l16  = threadIdx.x & 15;
    const uint32_t mask = 0xFFFFu << (((threadIdx.x >> 4) & 1) * 16);
    if (node >= N_NODES) { PDL_WAIT(); return; }
    const int w4 = l16 * 4;          // word offset in row (4 words = 16B)
    const int c  = l16 * 8;          // float column base

    const int beg = g_start[node];
    const int end = beg + g_cr[node];

    PDL_WAIT();

    float a[8];
    {
        uint4 sv = *(const uint4*)&xs16[(size_t)node * 64 + w4];
#pragma unroll
        for (int q = 0; q < 8; q++) a[q] = 0.f;
        acc8(a, sv);                 // self-loop
    }

    for (int base = beg; base < end; base += 16) {
        int idx = (base + l16 < end) ? g_csr[base + l16] : 0;
        int m = min(16, end - base);
        int j = 0;
        for (; j + 4 <= m; j += 4) {
            int s0 = __shfl_sync(mask, idx, j,     16);
            int s1 = __shfl_sync(mask, idx, j + 1, 16);
            int s2 = __shfl_sync(mask, idx, j + 2, 16);
            int s3 = __shfl_sync(mask, idx, j + 3, 16);
            uint4 v0 = *(const uint4*)&xs16[(size_t)s0 * 64 + w4];
            uint4 v1 = *(const uint4*)&xs16[(size_t)s1 * 64 + w4];
            uint4 v2 = *(const uint4*)&xs16[(size_t)s2 * 64 + w4];
            uint4 v3 = *(const uint4*)&xs16[(size_t)s3 * 64 + w4];
            acc8(a, v0); acc8(a, v1); acc8(a, v2); acc8(a, v3);
        }
        for (; j < m; j++) {
            int s = __shfl_sync(mask, idx, j, 16);
            uint4 v = *(const uint4*)&xs16[(size_t)s * 64 + w4];
            acc8(a, v);
        }
    }

    const float ir = g_invr[node];
    float y[8];
    {
        uint4 hv = *(const uint4*)&h16[(size_t)node * 64 + w4];
        float2 e;
        e = __half22float2(*(__half2*)&hv.x); y[0] = a[0] * ir + e.x; y[1] = a[1] * ir + e.y;
        e = __half22float2(*(__half2*)&hv.y); y[2] = a[2] * ir + e.x; y[3] = a[3] * ir + e.y;
        e = __half22float2(*(__half2*)&hv.z); y[4] = a[4] * ir + e.x; y[5] = a[5] * ir + e.y;
        e = __half22float2(*(__half2*)&hv.w); y[6] = a[6] * ir + e.x; y[7] = a[7] * ir + e.y;
    }

    float sum = 0.f, sq = 0.f;
#pragma unroll
    for (int q = 0; q < 8; q++) { sum += y[q]; sq += y[q] * y[q]; }
#pragma unroll
    for (int o = 8; o; o >>= 1) {
        sum += __shfl_xor_sync(mask, sum, o, 16);
        sq  += __shfl_xor_sync(mask, sq,  o, 16);
    }
    float mean = sum * (1.f / 128.f);
    float var  = sq * (1.f / 128.f) - mean * mean;
    float rs = rsqrtf(var + LN_EPS);

    float4 sc0 = *(const float4*)&scale[c];
    float4 sc1 = *(const float4*)&scale[c + 4];
    float4 of0 = *(const float4*)&offset[c];
    float4 of1 = *(const float4*)&offset[c + 4];
    float o0 = (y[0] - mean) * rs * sc0.x + of0.x;
    float o1 = (y[1] - mean) * rs * sc0.y + of0.y;
    float o2 = (y[2] - mean) * rs * sc0.z + of0.z;
    float o3 = (y[3] - mean) * rs * sc0.w + of0.w;
    float o4 = (y[4] - mean) * rs * sc1.x + of1.x;
    float o5 = (y[5] - mean) * rs * sc1.y + of1.y;
    float o6 = (y[6] - mean) * rs * sc1.z + of1.z;
    float o7 = (y[7] - mean) * rs * sc1.w + of1.w;

    uint4 outv;
    __half2 p;
    p = __floats2half2_rn(o0, o1); outv.x = *(uint32_t*)&p;
    p = __floats2half2_rn(o2, o3); outv.y = *(uint32_t*)&p;
    p = __floats2half2_rn(o4, o5); outv.z = *(uint32_t*)&p;
    p = __floats2half2_rn(o6, o7); outv.w = *(uint32_t*)&p;
    *(uint4*)&h16[(size_t)node * 64 + w4] = outv;
}

// ---------------- pool (fp16 h) + decode: 256 threads, 4-way row split ----------------
__global__ __launch_bounds__(256)
void k_pool(const uint32_t* __restrict__ h16, const float* __restrict__ dec_w,
            const float* __restrict__ dec_b, float* __restrict__ out) {
    PDL_TRIGGER();
    int g = blockIdx.x;
    int w   = threadIdx.x & 63;
    int seg = threadIdx.x >> 6;
    const int per = N_NODES / N_GRAPH;
    const uint32_t* base = h16 + (size_t)g * per * 64;
    float w0 = dec_w[2 * w], w1 = dec_w[2 * w + 1];
    float bb = dec_b[0];
    PDL_WAIT();
    float s0 = 0.f, s1 = 0.f;
    for (int r = seg; r < per; r += 4) {
        uint32_t v = base[(size_t)r * 64 + w];
        float2 f = __half22float2(*(__half2*)&v);
        s0 += f.x; s1 += f.y;
    }
    float val = (s0 * w0 + s1 * w1) * (1.f / (float)per);
    __shared__ float red[8];
#pragma unroll
    for (int o = 16; o; o >>= 1) val += __shfl_xor_sync(0xffffffffu, val, o);
    if ((threadIdx.x & 31) == 0) red[threadIdx.x >> 5] = val;
    __syncthreads();
    if (threadIdx.x == 0) {
        float t = 0.f;
#pragma unroll
        for (int i = 0; i < 8; i++) t += red[i];
        out[g] = t + bb;
    }
}

// ---------------- launch ----------------
template<typename... Args>
static void launch_pdl(void (*kern)(Args...), dim3 grid, dim3 block, size_t smem,
                       Args... args) {
    cudaLaunchConfig_t cfg = {};
    cfg.gridDim = grid;
    cfg.blockDim = block;
    cfg.dynamicSmemBytes = smem;
    cfg.stream = 0;
    cudaLaunchAttribute at[1];
    at[0].id = cudaLaunchAttributeProgrammaticStreamSerialization;
    at[0].val.programmaticStreamSerializationAllowed = 1;
    cfg.attrs = at;
    cfg.numAttrs = 1;
    cudaLaunchKernelEx(&cfg, kern, args...);
}

extern "C" void kernel_launch(void* const* d_in, const int* in_sizes, int n_in,
                              void* d_out, int out_size) {
    const float* nodes     = (const float*)d_in[0];
    const int*   senders   = (const int*)d_in[1];
    const int*   receivers = (const int*)d_in[2];
    const float* embed_w   = (const float*)d_in[4];
    const float* embed_b   = (const float*)d_in[5];
    const float* mlp_w     = (const float*)d_in[6];
    const float* mlp_b     = (const float*)d_in[7];
    const float* ln_scale  = (const float*)d_in[8];
    const float* ln_offset = (const float*)d_in[9];
    const float* dec_w     = (const float*)d_in[10];
    const float* dec_b     = (const float*)d_in[11];
    float* out = (float*)d_out;

    uint32_t *ph16, *px16, *pwhi, *pwlo;
    cudaGetSymbolAddress((void**)&ph16, g_h16);
    cudaGetSymbolAddress((void**)&px16, g_x16);
    cudaGetSymbolAddress((void**)&pwhi, g_whi);
    cudaGetSymbolAddress((void**)&pwlo, g_wlo);

    cudaFuncSetAttribute(k_embed, cudaFuncAttributeMaxDynamicSharedMemorySize, SM_EMBED);
    cudaFuncSetAttribute(k_mlp,   cudaFuncAttributeMaxDynamicSharedMemorySize, SM_MLP);

    static cudaStream_t s2 = nullptr;
    static cudaEvent_t evFork = nullptr, evInv = nullptr, evJoin = nullptr;
    if (!s2) {
        cudaStreamCreateWithFlags(&s2, cudaStreamNonBlocking);
        cudaEventCreateWithFlags(&evFork, cudaEventDisableTiming);
        cudaEventCreateWithFlags(&evInv, cudaEventDisableTiming);
        cudaEventCreateWithFlags(&evJoin, cudaEventDisableTiming);
    }

    // ---- fork: CSR build on s2 ----
    cudaEventRecord(evFork, 0);
    cudaStreamWaitEvent(s2, evFork, 0);
    k_zero_deg<<<(N_NODES + 255) / 256, 256, 0, s2>>>();
    k_count<<<(N_EDGES / 4 + 255) / 256, 256, 0, s2>>>(senders, receivers);
    k_inv<<<(N_NODES + 255) / 256, 256, 0, s2>>>();
    cudaEventRecord(evInv, s2);
    k_fill<<<(N_EDGES / 4 + 255) / 256, 256, 0, s2>>>(senders, receivers);
    cudaEventRecord(evJoin, s2);

    const int gemm_grid = (N_NODES + 127) / 128;

    k_wconv<<<(WCONV_WORDS + 255) / 256, 256>>>(embed_w, mlp_w);
    k_embed<<<gemm_grid, 512, SM_EMBED>>>(nodes, pwhi, pwlo, embed_b, ph16, N_NODES);

    const uint32_t* whi_mlp[4];
    const uint32_t* wlo_mlp[4];
    for (int g = 0; g < 4; g++) {
        whi_mlp[g] = pwhi + 4096 + g * 8192;
        wlo_mlp[g] = pwlo + 4096 + g * 8192;
    }

    const int row_grid = (N_NODES * 16 + 255) / 256;   // half-warp per node

    cudaStreamWaitEvent(0, evInv, 0);

    for (int s = 0; s < 2; s++) {
        const float* b0 = mlp_b + (size_t)(s * 2 + 0) * LATENT;
        const float* b1 = mlp_b + (size_t)(s * 2 + 1) * LATENT;

        launch_pdl(k_mlp, dim3(gemm_grid), dim3(512), (size_t)SM_MLP,
                   (const uint32_t*)ph16,
                   whi_mlp[s * 2], wlo_mlp[s * 2],
                   whi_mlp[s * 2 + 1], wlo_mlp[s * 2 + 1],
                   b0, b1, px16, (int)N_NODES);
        if (s == 0) cudaStreamWaitEvent(0, evJoin, 0);
        launch_pdl(k_gln, dim3(row_grid), dim3(256), (size_t)0,
                   (const uint32_t*)px16, ph16,
                   (const float*)(ln_scale + s * LATENT),
                   (const float*)(ln_offset + s * LATENT));
    }

    launch_pdl(k_pool, dim3(N_GRAPH), dim3(256), (size_t)0,
               (const uint32_t*)ph16, dec_w, dec_b, out);
}